// round 1
// baseline (speedup 1.0000x reference)
#include <cuda_runtime.h>
#include <cstddef>

// Problem dims (fixed by the reference)
#define BATCH 16
#define NVERT 250000
#define NFACE 500000

// Scratch: __device__ globals (no allocation allowed in kernel_launch)
__device__ float g_acc[(size_t)BATCH * NVERT * 3];  // neighbor sums, 48 MB
__device__ float g_deg[NVERT];                      // degree (float), 1 MB

// ---------------------------------------------------------------------------
// Zero the accumulators (float4-vectorized; sizes are multiples of 4)
// ---------------------------------------------------------------------------
__global__ void zero_acc_kernel() {
    size_t i = (size_t)blockIdx.x * blockDim.x + threadIdx.x;
    size_t n4 = (size_t)BATCH * NVERT * 3 / 4;  // 12,000,000 / 4
    if (i < n4) {
        reinterpret_cast<float4*>(g_acc)[i] = make_float4(0.f, 0.f, 0.f, 0.f);
    }
    if (i < NVERT) {
        g_deg[i] = 0.f;
    }
}

// ---------------------------------------------------------------------------
// Degree: each face contributes +2 to each of its 3 vertices
// (dst list contains each face-vertex exactly twice)
// ---------------------------------------------------------------------------
__global__ void deg_kernel(const int* __restrict__ faces) {
    int f = blockIdx.x * blockDim.x + threadIdx.x;
    if (f >= NFACE) return;
    int a = faces[3 * f + 0];
    int b = faces[3 * f + 1];
    int c = faces[3 * f + 2];
    atomicAdd(&g_deg[a], 2.0f);
    atomicAdd(&g_deg[b], 2.0f);
    atomicAdd(&g_deg[c], 2.0f);
}

// ---------------------------------------------------------------------------
// Scatter: per (face, batch), accumulate neighbor sums.
//   neigh_sum[a] += v_b + v_c ; neigh_sum[b] += v_a + v_c ; neigh_sum[c] += v_a + v_b
// grid.y = batch, grid.x covers faces. Per-batch vertex slice (3 MB) is
// L2-resident, so the random gathers are L2 hits.
// ---------------------------------------------------------------------------
__global__ void scatter_kernel(const float* __restrict__ vert,
                               const int* __restrict__ faces) {
    int f = blockIdx.x * blockDim.x + threadIdx.x;
    if (f >= NFACE) return;
    int bb = blockIdx.y;

    int ia = faces[3 * f + 0];
    int ib = faces[3 * f + 1];
    int ic = faces[3 * f + 2];

    const float* vb = vert + (size_t)bb * NVERT * 3;
    float ax = vb[3 * ia + 0], ay = vb[3 * ia + 1], az = vb[3 * ia + 2];
    float bx = vb[3 * ib + 0], by = vb[3 * ib + 1], bz = vb[3 * ib + 2];
    float cx = vb[3 * ic + 0], cy = vb[3 * ic + 1], cz = vb[3 * ic + 2];

    float* acc = g_acc + (size_t)bb * NVERT * 3;

    atomicAdd(&acc[3 * ia + 0], bx + cx);
    atomicAdd(&acc[3 * ia + 1], by + cy);
    atomicAdd(&acc[3 * ia + 2], bz + cz);

    atomicAdd(&acc[3 * ib + 0], ax + cx);
    atomicAdd(&acc[3 * ib + 1], ay + cy);
    atomicAdd(&acc[3 * ib + 2], az + cz);

    atomicAdd(&acc[3 * ic + 0], ax + bx);
    atomicAdd(&acc[3 * ic + 1], ay + by);
    atomicAdd(&acc[3 * ic + 2], az + bz);
}

// ---------------------------------------------------------------------------
// Finalize: lap = acc/max(deg,1) - vert ; out = ||lap||_2
// Fully coalesced streaming pass.
// ---------------------------------------------------------------------------
__global__ void finalize_kernel(const float* __restrict__ vert,
                                float* __restrict__ out) {
    size_t i = (size_t)blockIdx.x * blockDim.x + threadIdx.x;  // over B*N
    if (i >= (size_t)BATCH * NVERT) return;
    int n = (int)(i % NVERT);
    float d = fmaxf(g_deg[n], 1.0f);
    float inv = 1.0f / d;

    float lx = g_acc[3 * i + 0] * inv - vert[3 * i + 0];
    float ly = g_acc[3 * i + 1] * inv - vert[3 * i + 1];
    float lz = g_acc[3 * i + 2] * inv - vert[3 * i + 2];

    out[i] = sqrtf(lx * lx + ly * ly + lz * lz);
}

// ---------------------------------------------------------------------------
extern "C" void kernel_launch(void* const* d_in, const int* in_sizes, int n_in,
                              void* d_out, int out_size) {
    const float* vert = (const float*)d_in[0];
    const int* faces = (const int*)d_in[1];
    float* out = (float*)d_out;

    // Zero accumulators
    {
        size_t n4 = (size_t)BATCH * NVERT * 3 / 4;  // 3,000,000
        int threads = 256;
        int blocks = (int)((n4 + threads - 1) / threads);
        zero_acc_kernel<<<blocks, threads>>>();
    }

    // Degree
    {
        int threads = 256;
        int blocks = (NFACE + threads - 1) / threads;
        deg_kernel<<<blocks, threads>>>(faces);
    }

    // Scatter neighbor sums (grid.y = batch)
    {
        int threads = 256;
        dim3 grid((NFACE + threads - 1) / threads, BATCH);
        scatter_kernel<<<grid, threads>>>(vert, faces);
    }

    // Finalize
    {
        size_t total = (size_t)BATCH * NVERT;
        int threads = 256;
        int blocks = (int)((total + threads - 1) / threads);
        finalize_kernel<<<blocks, threads>>>(vert, out);
    }
}